// round 14
// baseline (speedup 1.0000x reference)
#include <cuda_runtime.h>
#include <math.h>

#define H 1024
#define W 1024
#define NB 4
#define NPIX (H*W)          /* 1048576 = 2^20 */
#define TOT  (NB*NPIX)      /* 4194304 */

// ---------------- scratch (static device globals; no runtime allocation) -----
__device__ float    g_blur[TOT];      // 16 MB
__device__ int      g_state[TOT];     // 16 MB   0=none 1=weak 2=strong
__device__ unsigned g_queue[TOT];     // 16 MB   BFS queue slots
__device__ unsigned g_qhead, g_qtail, g_qproc, g_bar1, g_bar2;

// neighbor offsets for direction k = round(angle/45) mod 8
// k: 0:(0,1) 1:(-1,1) 2:(-1,0) 3:(-1,-1) 4:(0,-1) 5:(1,-1) 6:(1,0) 7:(1,1)
__constant__ int c_dr[8] = {0,-1,-1,-1, 0, 1, 1, 1};
__constant__ int c_dc[8] = {1, 1, 0,-1,-1,-1, 0, 1};

struct GaussW { float w[25]; };

// ---------------- stage 1: grayscale + 5x5 gaussian, reflect padding --------
__global__ void k_gray_blur(const float* __restrict__ x, GaussW gw) {
    __shared__ float s[36][37];
    const int bx = blockIdx.x * 32, by = blockIdx.y * 32, b = blockIdx.z;
    const float* xr = x + (size_t)b * 3 * NPIX;
    const int tid = threadIdx.y * 32 + threadIdx.x;

    for (int i = tid; i < 36 * 36; i += 256) {
        int r = i / 36, c = i - r * 36;
        int gy = by - 2 + r, gx = bx - 2 + c;
        gy = gy < 0 ? -gy : (gy > H - 1 ? 2 * (H - 1) - gy : gy);   // numpy 'reflect'
        gx = gx < 0 ? -gx : (gx > W - 1 ? 2 * (W - 1) - gx : gx);
        int idx = gy * W + gx;
        s[r][c] = 0.299f * xr[idx] + 0.587f * xr[NPIX + idx] + 0.114f * xr[2 * NPIX + idx];
    }
    __syncthreads();

    const int tx = threadIdx.x;
    for (int k = 0; k < 4; k++) {
        int oy = threadIdx.y + 8 * k;
        float acc = 0.f;
        #pragma unroll
        for (int r = 0; r < 5; r++)
            #pragma unroll
            for (int c = 0; c < 5; c++)
                acc += gw.w[r * 5 + c] * s[oy + r][tx + c];
        g_blur[(size_t)b * NPIX + (size_t)(by + oy) * W + bx + tx] = acc;
    }
}

// ------- stage 2: sobel (edge pad) + magnitude + NMS + thresholds -----------
__global__ void k_sobel_nms(float* __restrict__ outMag) {
    __shared__ float bs[36][37];   // blurred, edge-clamped, halo 2
    __shared__ float ms[34][35];   // magnitude (0 outside image), halo 1
    __shared__ float gxs[34][35];
    __shared__ float gys[34][35];
    const int bx = blockIdx.x * 32, by = blockIdx.y * 32, b = blockIdx.z;
    const float* bl = g_blur + (size_t)b * NPIX;
    const int tid = threadIdx.y * 32 + threadIdx.x;

    for (int i = tid; i < 36 * 36; i += 256) {
        int r = i / 36, c = i - r * 36;
        int gy = min(max(by - 2 + r, 0), H - 1);   // 'edge' padding
        int gx = min(max(bx - 2 + c, 0), W - 1);
        bs[r][c] = bl[gy * W + gx];
    }
    __syncthreads();

    for (int i = tid; i < 34 * 34; i += 256) {
        int r = i / 34, c = i - r * 34;
        int iy = by - 1 + r, ix = bx - 1 + c;
        float m = 0.f, gxv = 0.f, gyv = 0.f;
        if ((unsigned)iy < (unsigned)H && (unsigned)ix < (unsigned)W) {
            float a00 = bs[r][c],     a01 = bs[r][c + 1],     a02 = bs[r][c + 2];
            float a10 = bs[r + 1][c],                         a12 = bs[r + 1][c + 2];
            float a20 = bs[r + 2][c], a21 = bs[r + 2][c + 1], a22 = bs[r + 2][c + 2];
            gxv = (a02 - a00) + 2.f * (a12 - a10) + (a22 - a20);
            gyv = (a20 - a00) + 2.f * (a21 - a01) + (a22 - a02);
            m = sqrtf(gxv * gxv + gyv * gyv + 1e-6f);
        }
        ms[r][c] = m; gxs[r][c] = gxv; gys[r][c] = gyv;
    }
    __syncthreads();

    const int tx = threadIdx.x;
    for (int k = 0; k < 4; k++) {
        int oy = threadIdx.y + 8 * k;
        int r = oy + 1, c = tx + 1;
        float gxv = gxs[r][c], gyv = gys[r][c];
        float deg = atan2f(gyv, gxv) * 57.29577951308232f;   // jnp.degrees
        int kk = (int)rintf(deg / 45.0f);                    // jnp.round (half-even)
        int pos = kk & 7, neg = (kk + 4) & 7;
        float mc = ms[r][c];
        float csp = mc - ms[r + c_dr[pos]][c + c_dc[pos]];
        float csn = mc - ms[r + c_dr[neg]][c + c_dc[neg]];
        float mo = (fminf(csp, csn) > 0.0f) ? mc : 0.0f;
        int oidx = b * NPIX + (by + oy) * W + bx + tx;
        outMag[oidx] = mo;
        g_state[oidx] = (mo > 0.2f) ? 2 : ((mo > 0.1f) ? 1 : 0);
    }
}

// ---------------- stage 3: hysteresis = closure of strong through weak ------
__global__ void k_reset() {
    if (threadIdx.x == 0) { g_qhead = 0; g_qtail = 0; g_qproc = 0; g_bar1 = 0; g_bar2 = 0; }
}

// 128 blocks x 256 threads: <= SM count, all co-resident -> software barrier ok
__global__ void __launch_bounds__(256, 1) k_hyst(float* __restrict__ edges) {
    const int gtid = blockIdx.x * blockDim.x + threadIdx.x;
    const int nthr = gridDim.x * blockDim.x;

    // phase 0: clear queue sentinels
    for (int i = gtid; i < TOT; i += nthr) g_queue[i] = 0xFFFFFFFFu;

    __syncthreads();
    if (threadIdx.x == 0) {
        __threadfence();
        atomicAdd(&g_bar1, 1u);
        while (atomicAdd(&g_bar1, 0u) < gridDim.x) { }
    }
    __syncthreads();

    // phase 1: seed sweep — promote weak pixels touching strong, enqueue them
    for (int i = gtid; i < TOT; i += nthr) {
        if (__ldcg(&g_state[i]) == 1) {
            int y = (i >> 10) & 1023, xx = i & 1023;
            int base = i & ~(NPIX - 1);
            bool near_strong = false;
            #pragma unroll
            for (int d = 0; d < 8; d++) {
                int ny = y + c_dr[d], nx = xx + c_dc[d];
                if ((unsigned)ny < 1024u && (unsigned)nx < 1024u &&
                    __ldcg(&g_state[base + (ny << 10) + nx]) == 2)
                    near_strong = true;
            }
            if (near_strong && atomicCAS(&g_state[i], 1, 2) == 1) {
                unsigned pos = atomicAdd(&g_qtail, 1u);
                ((volatile unsigned*)g_queue)[pos] = (unsigned)i;
            }
        }
    }

    __syncthreads();
    if (threadIdx.x == 0) {
        __threadfence();
        atomicAdd(&g_bar2, 1u);
        while (atomicAdd(&g_bar2, 0u) < gridDim.x) { }
    }
    __syncthreads();

    // phase 2: async BFS over the work queue
    bool done = false;
    while (!done) {
        unsigned t = atomicAdd(&g_qhead, 1u);
        for (;;) {
            unsigned tail = *(volatile unsigned*)&g_qtail;
            if (t < tail) break;
            unsigned p = *(volatile unsigned*)&g_qproc;      // read proc BEFORE tail
            unsigned tail2 = *(volatile unsigned*)&g_qtail;
            if (p == tail2 && t >= tail2) { done = true; break; }  // fully drained
            __nanosleep(64);
        }
        if (done) break;
        unsigned v;
        while ((v = ((volatile unsigned*)g_queue)[t]) == 0xFFFFFFFFu) { }
        int y = (v >> 10) & 1023, xx = v & 1023;
        int base = (int)(v & ~(unsigned)(NPIX - 1));
        #pragma unroll
        for (int d = 0; d < 8; d++) {
            int ny = y + c_dr[d], nx = xx + c_dc[d];
            if ((unsigned)ny < 1024u && (unsigned)nx < 1024u) {
                int ni = base + (ny << 10) + nx;
                if (__ldcg(&g_state[ni]) == 1 && atomicCAS(&g_state[ni], 1, 2) == 1) {
                    unsigned pos = atomicAdd(&g_qtail, 1u);
                    ((volatile unsigned*)g_queue)[pos] = (unsigned)ni;
                }
            }
        }
        __threadfence();               // CAS + slot writes visible before proc count
        atomicAdd(&g_qproc, 1u);
    }

    // phase 3: state is final once drained — write edges
    __threadfence();
    for (int i = gtid; i < TOT; i += nthr)
        edges[i] = (__ldcg(&g_state[i]) == 2) ? 1.0f : 0.0f;
}

// ---------------------------------------------------------------------------
extern "C" void kernel_launch(void* const* d_in, const int* in_sizes, int n_in,
                              void* d_out, int out_size) {
    const float* x = (const float*)d_in[0];
    float* out = (float*)d_out;

    // Gaussian weights, replicating numpy float32 construction
    GaussW gw;
    float g1[5];
    for (int i = 0; i < 5; i++) {
        double d = (double)i - 2.0;
        g1[i] = (float)exp(-d * d / 2.0);
    }
    float s = 0.f;
    for (int i = 0; i < 5; i++) s += g1[i];
    for (int i = 0; i < 5; i++) g1[i] = g1[i] / s;
    for (int i = 0; i < 5; i++)
        for (int j = 0; j < 5; j++)
            gw.w[i * 5 + j] = g1[i] * g1[j];

    dim3 blk(32, 8), grd(32, 32, NB);
    k_gray_blur<<<grd, blk>>>(x, gw);
    k_sobel_nms<<<grd, blk>>>(out);            // magnitude -> out[0 .. TOT)
    k_reset<<<1, 32>>>();
    k_hyst<<<128, 256>>>(out + TOT);           // edges -> out[TOT .. 2*TOT)
    (void)in_sizes; (void)n_in; (void)out_size;
}

// round 15
// speedup vs baseline: 1.0076x; 1.0076x over previous
#include <cuda_runtime.h>
#include <math.h>

#define H 1024
#define W 1024
#define NB 4
#define NPIX (H*W)          /* 1048576 = 2^20 */
#define TOT  (NB*NPIX)      /* 4194304 */

// ---------------- scratch (static device globals; no runtime allocation) -----
__device__ float    g_blur[TOT];      // 16 MB
__device__ int      g_state[TOT];     // 16 MB   0=none 1=weak 2=strong
__device__ unsigned g_queue[TOT];     // 16 MB   BFS queue slots
__device__ unsigned g_qhead, g_qtail, g_qproc, g_bar1, g_bar2;

// neighbor offsets for direction k = round(angle/45) mod 8
// k: 0:(0,1) 1:(-1,1) 2:(-1,0) 3:(-1,-1) 4:(0,-1) 5:(1,-1) 6:(1,0) 7:(1,1)
__constant__ int c_dr[8] = {0,-1,-1,-1, 0, 1, 1, 1};
__constant__ int c_dc[8] = {1, 1, 0,-1,-1,-1, 0, 1};

struct GaussW { float w[25]; };

// ---------------- stage 1: grayscale + 5x5 gaussian, reflect padding --------
__global__ void k_gray_blur(const float* __restrict__ x, GaussW gw) {
    __shared__ float s[36][37];
    const int bx = blockIdx.x * 32, by = blockIdx.y * 32, b = blockIdx.z;
    const float* xr = x + (size_t)b * 3 * NPIX;
    const int tid = threadIdx.y * 32 + threadIdx.x;

    for (int i = tid; i < 36 * 36; i += 256) {
        int r = i / 36, c = i - r * 36;
        int gy = by - 2 + r, gx = bx - 2 + c;
        gy = gy < 0 ? -gy : (gy > H - 1 ? 2 * (H - 1) - gy : gy);   // numpy 'reflect'
        gx = gx < 0 ? -gx : (gx > W - 1 ? 2 * (W - 1) - gx : gx);
        int idx = gy * W + gx;
        s[r][c] = 0.299f * xr[idx] + 0.587f * xr[NPIX + idx] + 0.114f * xr[2 * NPIX + idx];
    }
    __syncthreads();

    const int tx = threadIdx.x;
    for (int k = 0; k < 4; k++) {
        int oy = threadIdx.y + 8 * k;
        float acc = 0.f;
        #pragma unroll
        for (int r = 0; r < 5; r++)
            #pragma unroll
            for (int c = 0; c < 5; c++)
                acc += gw.w[r * 5 + c] * s[oy + r][tx + c];
        g_blur[(size_t)b * NPIX + (size_t)(by + oy) * W + bx + tx] = acc;
    }
}

// ------- stage 2: sobel (edge pad) + magnitude + NMS + thresholds -----------
__global__ void k_sobel_nms(float* __restrict__ outMag) {
    __shared__ float bs[36][37];   // blurred, edge-clamped, halo 2
    __shared__ float ms[34][35];   // magnitude (0 outside image), halo 1
    __shared__ float gxs[34][35];
    __shared__ float gys[34][35];
    const int bx = blockIdx.x * 32, by = blockIdx.y * 32, b = blockIdx.z;
    const float* bl = g_blur + (size_t)b * NPIX;
    const int tid = threadIdx.y * 32 + threadIdx.x;

    for (int i = tid; i < 36 * 36; i += 256) {
        int r = i / 36, c = i - r * 36;
        int gy = min(max(by - 2 + r, 0), H - 1);   // 'edge' padding
        int gx = min(max(bx - 2 + c, 0), W - 1);
        bs[r][c] = bl[gy * W + gx];
    }
    __syncthreads();

    for (int i = tid; i < 34 * 34; i += 256) {
        int r = i / 34, c = i - r * 34;
        int iy = by - 1 + r, ix = bx - 1 + c;
        float m = 0.f, gxv = 0.f, gyv = 0.f;
        if ((unsigned)iy < (unsigned)H && (unsigned)ix < (unsigned)W) {
            float a00 = bs[r][c],     a01 = bs[r][c + 1],     a02 = bs[r][c + 2];
            float a10 = bs[r + 1][c],                         a12 = bs[r + 1][c + 2];
            float a20 = bs[r + 2][c], a21 = bs[r + 2][c + 1], a22 = bs[r + 2][c + 2];
            gxv = (a02 - a00) + 2.f * (a12 - a10) + (a22 - a20);
            gyv = (a20 - a00) + 2.f * (a21 - a01) + (a22 - a02);
            m = sqrtf(gxv * gxv + gyv * gyv + 1e-6f);
        }
        ms[r][c] = m; gxs[r][c] = gxv; gys[r][c] = gyv;
    }
    __syncthreads();

    const int tx = threadIdx.x;
    for (int k = 0; k < 4; k++) {
        int oy = threadIdx.y + 8 * k;
        int r = oy + 1, c = tx + 1;
        float gxv = gxs[r][c], gyv = gys[r][c];
        float deg = atan2f(gyv, gxv) * 57.29577951308232f;   // jnp.degrees
        int kk = (int)rintf(deg / 45.0f);                    // jnp.round (half-even)
        int pos = kk & 7, neg = (kk + 4) & 7;
        float mc = ms[r][c];
        float csp = mc - ms[r + c_dr[pos]][c + c_dc[pos]];
        float csn = mc - ms[r + c_dr[neg]][c + c_dc[neg]];
        float mo = (fminf(csp, csn) > 0.0f) ? mc : 0.0f;
        int oidx = b * NPIX + (by + oy) * W + bx + tx;
        outMag[oidx] = mo;
        g_state[oidx] = (mo > 0.2f) ? 2 : ((mo > 0.1f) ? 1 : 0);
    }
}

// ---------------- stage 3: hysteresis = closure of strong through weak ------
__global__ void k_reset() {
    if (threadIdx.x == 0) { g_qhead = 0; g_qtail = 0; g_qproc = 0; g_bar1 = 0; g_bar2 = 0; }
}

// 128 blocks x 256 threads: <= SM count, all co-resident -> software barrier ok
__global__ void __launch_bounds__(256, 1) k_hyst(float* __restrict__ edges) {
    const int gtid = blockIdx.x * blockDim.x + threadIdx.x;
    const int nthr = gridDim.x * blockDim.x;

    // phase 0: clear queue sentinels
    for (int i = gtid; i < TOT; i += nthr) g_queue[i] = 0xFFFFFFFFu;

    __syncthreads();
    if (threadIdx.x == 0) {
        __threadfence();
        atomicAdd(&g_bar1, 1u);
        while (atomicAdd(&g_bar1, 0u) < gridDim.x) { }
    }
    __syncthreads();

    // phase 1: seed sweep — promote weak pixels touching strong, enqueue them
    for (int i = gtid; i < TOT; i += nthr) {
        if (__ldcg(&g_state[i]) == 1) {
            int y = (i >> 10) & 1023, xx = i & 1023;
            int base = i & ~(NPIX - 1);
            bool near_strong = false;
            #pragma unroll
            for (int d = 0; d < 8; d++) {
                int ny = y + c_dr[d], nx = xx + c_dc[d];
                if ((unsigned)ny < 1024u && (unsigned)nx < 1024u &&
                    __ldcg(&g_state[base + (ny << 10) + nx]) == 2)
                    near_strong = true;
            }
            if (near_strong && atomicCAS(&g_state[i], 1, 2) == 1) {
                unsigned pos = atomicAdd(&g_qtail, 1u);
                ((volatile unsigned*)g_queue)[pos] = (unsigned)i;
            }
        }
    }

    __syncthreads();
    if (threadIdx.x == 0) {
        __threadfence();
        atomicAdd(&g_bar2, 1u);
        while (atomicAdd(&g_bar2, 0u) < gridDim.x) { }
    }
    __syncthreads();

    // phase 2: async BFS over the work queue
    bool done = false;
    while (!done) {
        unsigned t = atomicAdd(&g_qhead, 1u);
        for (;;) {
            unsigned tail = *(volatile unsigned*)&g_qtail;
            if (t < tail) break;
            unsigned p = *(volatile unsigned*)&g_qproc;      // read proc BEFORE tail
            unsigned tail2 = *(volatile unsigned*)&g_qtail;
            if (p == tail2 && t >= tail2) { done = true; break; }  // fully drained
            __nanosleep(64);
        }
        if (done) break;
        unsigned v;
        while ((v = ((volatile unsigned*)g_queue)[t]) == 0xFFFFFFFFu) { }
        int y = (v >> 10) & 1023, xx = v & 1023;
        int base = (int)(v & ~(unsigned)(NPIX - 1));
        #pragma unroll
        for (int d = 0; d < 8; d++) {
            int ny = y + c_dr[d], nx = xx + c_dc[d];
            if ((unsigned)ny < 1024u && (unsigned)nx < 1024u) {
                int ni = base + (ny << 10) + nx;
                if (__ldcg(&g_state[ni]) == 1 && atomicCAS(&g_state[ni], 1, 2) == 1) {
                    unsigned pos = atomicAdd(&g_qtail, 1u);
                    ((volatile unsigned*)g_queue)[pos] = (unsigned)ni;
                }
            }
        }
        __threadfence();               // CAS + slot writes visible before proc count
        atomicAdd(&g_qproc, 1u);
    }

    // phase 3: state is final once drained — write edges
    __threadfence();
    for (int i = gtid; i < TOT; i += nthr)
        edges[i] = (__ldcg(&g_state[i]) == 2) ? 1.0f : 0.0f;
}

// ---------------------------------------------------------------------------
extern "C" void kernel_launch(void* const* d_in, const int* in_sizes, int n_in,
                              void* d_out, int out_size) {
    const float* x = (const float*)d_in[0];
    float* out = (float*)d_out;

    // Gaussian weights, replicating numpy float32 construction
    GaussW gw;
    float g1[5];
    for (int i = 0; i < 5; i++) {
        double d = (double)i - 2.0;
        g1[i] = (float)exp(-d * d / 2.0);
    }
    float s = 0.f;
    for (int i = 0; i < 5; i++) s += g1[i];
    for (int i = 0; i < 5; i++) g1[i] = g1[i] / s;
    for (int i = 0; i < 5; i++)
        for (int j = 0; j < 5; j++)
            gw.w[i * 5 + j] = g1[i] * g1[j];

    dim3 blk(32, 8), grd(32, 32, NB);
    k_gray_blur<<<grd, blk>>>(x, gw);
    k_sobel_nms<<<grd, blk>>>(out);            // magnitude -> out[0 .. TOT)
    k_reset<<<1, 32>>>();
    k_hyst<<<128, 256>>>(out + TOT);           // edges -> out[TOT .. 2*TOT)
    (void)in_sizes; (void)n_in; (void)out_size;
}

// round 16
// speedup vs baseline: 2.1603x; 2.1440x over previous
#include <cuda_runtime.h>
#include <math.h>

#define H 1024
#define W 1024
#define NB 4
#define NPIX (H*W)            /* 2^20 */
#define TOT  (NB*NPIX)        /* 4194304 */
#define WPR  32               /* 32-bit words per row */
#define NWORDS (NB*H*WPR)     /* 131072 */

// ---------------- scratch (static device globals; no runtime allocation) -----
__device__ unsigned g_sb[NWORDS];   // strong bit-plane (512 KB)
__device__ unsigned g_wb[NWORDS];   // weak-only bit-plane (512 KB)
__device__ unsigned g_bar, g_epoch, g_flag[2];

// NMS neighbor offsets for direction k = round(angle/45) mod 8
__constant__ int c_dr[8] = {0,-1,-1,-1, 0, 1, 1, 1};
__constant__ int c_dc[8] = {1, 1, 0,-1,-1,-1, 0, 1};

struct GaussW { float w[25]; };

// ---- fused: grayscale + 5x5 gaussian(reflect) + sobel(edge) + NMS + seed ----
__global__ void k_front(const float* __restrict__ x, GaussW gw,
                        float* __restrict__ outMag) {
    __shared__ float gs[40][41];            // gray, reflect halo 4
    __shared__ float bs[36][37];            // blur at clamped coords (== edge pad)
    __shared__ float ms[34][35];            // magnitude (0 outside image)
    __shared__ float gxs[34][35];
    __shared__ float gys[34][35];
    const int bx = blockIdx.x * 32, by = blockIdx.y * 32, b = blockIdx.z;
    const float* xr = x + (size_t)b * 3 * NPIX;
    const int tid = threadIdx.y * 32 + threadIdx.x;

    for (int i = tid; i < 40 * 40; i += 256) {
        int r = i / 40, c = i - r * 40;
        int gy = by - 4 + r, gx = bx - 4 + c;
        gy = gy < 0 ? -gy : (gy > H - 1 ? 2 * (H - 1) - gy : gy);   // 'reflect'
        gx = gx < 0 ? -gx : (gx > W - 1 ? 2 * (W - 1) - gx : gx);
        int idx = gy * W + gx;
        gs[r][c] = 0.299f * xr[idx] + 0.587f * xr[NPIX + idx] + 0.114f * xr[2 * NPIX + idx];
    }
    __syncthreads();

    // blur value at clamped coordinate == edge-padded blur (bit-identical to R15)
    for (int i = tid; i < 36 * 36; i += 256) {
        int r = i / 36, c = i - r * 36;
        int oy = min(max(by - 2 + r, 0), H - 1) - by + 4;   // gray-window row idx
        int ox = min(max(bx - 2 + c, 0), W - 1) - bx + 4;
        float acc = 0.f;
        #pragma unroll
        for (int dr = 0; dr < 5; dr++)
            #pragma unroll
            for (int dc = 0; dc < 5; dc++)
                acc += gw.w[dr * 5 + dc] * gs[oy - 2 + dr][ox - 2 + dc];
        bs[r][c] = acc;
    }
    __syncthreads();

    for (int i = tid; i < 34 * 34; i += 256) {
        int r = i / 34, c = i - r * 34;
        int iy = by - 1 + r, ix = bx - 1 + c;
        float m = 0.f, gxv = 0.f, gyv = 0.f;
        if ((unsigned)iy < (unsigned)H && (unsigned)ix < (unsigned)W) {
            float a00 = bs[r][c],     a01 = bs[r][c + 1],     a02 = bs[r][c + 2];
            float a10 = bs[r + 1][c],                         a12 = bs[r + 1][c + 2];
            float a20 = bs[r + 2][c], a21 = bs[r + 2][c + 1], a22 = bs[r + 2][c + 2];
            gxv = (a02 - a00) + 2.f * (a12 - a10) + (a22 - a20);
            gyv = (a20 - a00) + 2.f * (a21 - a01) + (a22 - a02);
            m = sqrtf(gxv * gxv + gyv * gyv + 1e-6f);
        }
        ms[r][c] = m; gxs[r][c] = gxv; gys[r][c] = gyv;
    }
    __syncthreads();

    const int tx = threadIdx.x;
    for (int k = 0; k < 4; k++) {
        int oy = threadIdx.y + 8 * k;
        int r = oy + 1, c = tx + 1;
        float gxv = gxs[r][c], gyv = gys[r][c];
        float deg = atan2f(gyv, gxv) * 57.29577951308232f;
        int kk = (int)rintf(deg / 45.0f);                    // half-even like jnp.round
        int pos = kk & 7, neg = (kk + 4) & 7;
        float mc = ms[r][c];
        float csp = mc - ms[r + c_dr[pos]][c + c_dc[pos]];
        float csn = mc - ms[r + c_dr[neg]][c + c_dc[neg]];
        float mo = (fminf(csp, csn) > 0.0f) ? mc : 0.0f;
        outMag[b * NPIX + (by + oy) * W + bx + tx] = mo;

        bool strong = mo > 0.2f;
        bool weak   = (mo > 0.1f) && !strong;
        unsigned sbits = __ballot_sync(0xffffffffu, strong);
        unsigned wbits = __ballot_sync(0xffffffffu, weak);
        if (tx == 0) {
            int wrow = ((b << 10) + by + oy) * WPR + blockIdx.x;
            g_sb[wrow] = sbits;
            g_wb[wrow] = wbits;
        }
    }
}

__global__ void k_reset() {
    if (threadIdx.x == 0) { g_bar = 0; g_epoch = 0; g_flag[0] = 0; g_flag[1] = 0; }
}

// -------- hysteresis: warp-per-tile bit-parallel flood fill, pass until stable
// 128 blocks x 256 threads (8 warps) <= 148 SMs -> co-resident, sw barrier ok.
__global__ void __launch_bounds__(256, 1) k_hyst(float* __restrict__ edges) {
    const int tid = threadIdx.x;
    const int wid = tid >> 5, lane = tid & 31;
    const int gwarp = blockIdx.x * 8 + wid;     // 0..1023
    const unsigned F = 0xffffffffu;
    __shared__ int s_flag;
    __shared__ unsigned s_f;

    unsigned pass = 0;
    for (;;) {
        if (tid == 0) s_flag = 0;
        __syncthreads();

        bool warp_ch = false;
        for (int t = gwarp; t < NB * 32 * 32; t += 1024) {
            int wx = t & 31, ty = (t >> 5) & 31, b = t >> 10;
            int y = ty * 32 + lane;
            int row = ((b << 10) + y) * WPR + wx;
            unsigned Cs = __ldcg(&g_sb[row]);
            unsigned Cw = __ldcg(&g_wb[row]);
            unsigned Ls = wx > 0  ? __ldcg(&g_sb[row - 1]) : 0u;
            unsigned Rs = wx < 31 ? __ldcg(&g_sb[row + 1]) : 0u;
            unsigned Us = 0, ULs = 0, URs = 0, Ds = 0, DLs = 0, DRs = 0;
            if (lane == 0 && ty > 0) {
                Us = __ldcg(&g_sb[row - WPR]);
                if (wx > 0)  ULs = __ldcg(&g_sb[row - WPR - 1]);
                if (wx < 31) URs = __ldcg(&g_sb[row - WPR + 1]);
            }
            if (lane == 31 && ty < 31) {
                Ds = __ldcg(&g_sb[row + WPR]);
                if (wx > 0)  DLs = __ldcg(&g_sb[row + WPR - 1]);
                if (wx < 31) DRs = __ldcg(&g_sb[row + WPR + 1]);
            }
            // fixed halo dilation (left/right word edge bits + up/down halo rows)
            unsigned myLR = ((Ls >> 31) & 1u) | ((Rs & 1u) << 31);
            unsigned upLR = __shfl_up_sync(F, myLR, 1);
            unsigned dnLR = __shfl_down_sync(F, myLR, 1);
            if (lane == 0)  upLR = ((ULs >> 31) & 1u) | ((URs & 1u) << 31);
            if (lane == 31) dnLR = ((DLs >> 31) & 1u) | ((DRs & 1u) << 31);
            unsigned Hfix = myLR | upLR | dnLR;
            if (lane == 0)  Hfix |= Us | (Us << 1) | (Us >> 1);
            if (lane == 31) Hfix |= Ds | (Ds << 1) | (Ds >> 1);

            unsigned S = Cs;
            for (;;) {
                unsigned up = __shfl_up_sync(F, S, 1);   if (lane == 0)  up = 0;
                unsigned dn = __shfl_down_sync(F, S, 1); if (lane == 31) dn = 0;
                unsigned a = up | dn;
                unsigned dil = a | (a << 1) | (a >> 1) | (S << 1) | (S >> 1) | Hfix;
                unsigned nS = S | (Cw & dil);
                unsigned moved = __any_sync(F, nS != S);
                S = nS;
                if (!moved) break;
            }
            if (S != Cs) { __stcg(&g_sb[row], S); warp_ch = true; }
        }
        if (__any_sync(F, warp_ch) && lane == 0) s_flag = 1;
        __threadfence();
        __syncthreads();

        if (tid == 0) {
            if (s_flag) atomicOr(&g_flag[pass & 1], 1u);
            unsigned a = atomicAdd(&g_bar, 1u);
            unsigned target = pass + 1;
            if (a == gridDim.x - 1) {
                g_bar = 0;
                g_flag[(pass + 1) & 1] = 0;        // clean flag for next pass
                __threadfence();
                atomicAdd(&g_epoch, 1u);
            } else {
                while (*(volatile unsigned*)&g_epoch < target) __nanosleep(64);
            }
            s_f = *(volatile unsigned*)&g_flag[pass & 1];
        }
        __syncthreads();
        unsigned f = s_f;
        pass++;
        if (!f) break;
        __syncthreads();
    }

    // expand final strong bits to float edges (coalesced: warp word -> 32 floats)
    for (int wi = gwarp; wi < NWORDS; wi += 1024) {
        unsigned bits = __ldcg(&g_sb[wi]);
        edges[(size_t)wi * 32 + lane] = ((bits >> lane) & 1u) ? 1.0f : 0.0f;
    }
}

// ---------------------------------------------------------------------------
extern "C" void kernel_launch(void* const* d_in, const int* in_sizes, int n_in,
                              void* d_out, int out_size) {
    const float* x = (const float*)d_in[0];
    float* out = (float*)d_out;

    // Gaussian weights (identical construction to the validated kernel)
    GaussW gw;
    float g1[5];
    for (int i = 0; i < 5; i++) {
        double d = (double)i - 2.0;
        g1[i] = (float)exp(-d * d / 2.0);
    }
    float s = 0.f;
    for (int i = 0; i < 5; i++) s += g1[i];
    for (int i = 0; i < 5; i++) g1[i] = g1[i] / s;
    for (int i = 0; i < 5; i++)
        for (int j = 0; j < 5; j++)
            gw.w[i * 5 + j] = g1[i] * g1[j];

    dim3 blk(32, 8), grd(32, 32, NB);
    k_front<<<grd, blk>>>(x, gw, out);      // magnitude -> out[0 .. TOT)
    k_reset<<<1, 32>>>();
    k_hyst<<<128, 256>>>(out + TOT);        // edges -> out[TOT .. 2*TOT)
    (void)in_sizes; (void)n_in; (void)out_size;
}

// round 17
// speedup vs baseline: 2.4052x; 1.1133x over previous
#include <cuda_runtime.h>
#include <math.h>

#define H 1024
#define W 1024
#define NB 4
#define NPIX (H*W)            /* 2^20 */
#define TOT  (NB*NPIX)        /* 4194304 */
#define WPR  32               /* 32-bit words per image row */
#define NWORDS (NB*H*WPR)     /* 131072 */

// ---------------- scratch (static device globals; no runtime allocation) -----
__device__ unsigned g_sb[NWORDS];   // strong bit-plane (512 KB)
__device__ unsigned g_wb[NWORDS];   // weak-only bit-plane (512 KB)
__device__ unsigned g_bar, g_epoch, g_flag[2];

// NMS neighbor offsets for direction k = round(angle/45) mod 8
__constant__ int c_dr[8] = {0,-1,-1,-1, 0, 1, 1, 1};
__constant__ int c_dc[8] = {1, 1, 0,-1,-1,-1, 0, 1};

struct GaussW { float w[25]; };

// ---- fused: grayscale + 5x5 gaussian(reflect) + sobel(edge) + NMS + seed ----
__global__ void k_front(const float* __restrict__ x, GaussW gw,
                        float* __restrict__ outMag) {
    __shared__ float gs[40][41];            // gray, reflect halo 4
    __shared__ float bs[36][37];            // blur at clamped coords (== edge pad)
    __shared__ float ms[34][35];            // magnitude (0 outside image)
    const int bx = blockIdx.x * 32, by = blockIdx.y * 32, b = blockIdx.z;
    const float* xr = x + (size_t)b * 3 * NPIX;
    const int tid = threadIdx.y * 32 + threadIdx.x;

    for (int i = tid; i < 40 * 40; i += 256) {
        int r = i / 40, c = i - r * 40;
        int gy = by - 4 + r, gx = bx - 4 + c;
        gy = gy < 0 ? -gy : (gy > H - 1 ? 2 * (H - 1) - gy : gy);   // 'reflect'
        gx = gx < 0 ? -gx : (gx > W - 1 ? 2 * (W - 1) - gx : gx);
        int idx = gy * W + gx;
        gs[r][c] = 0.299f * xr[idx] + 0.587f * xr[NPIX + idx] + 0.114f * xr[2 * NPIX + idx];
    }
    __syncthreads();

    // blur value at clamped coordinate == edge-padded blur (bit-identical)
    for (int i = tid; i < 36 * 36; i += 256) {
        int r = i / 36, c = i - r * 36;
        int oy = min(max(by - 2 + r, 0), H - 1) - by + 4;   // gray-window row idx
        int ox = min(max(bx - 2 + c, 0), W - 1) - bx + 4;
        float acc = 0.f;
        #pragma unroll
        for (int dr = 0; dr < 5; dr++)
            #pragma unroll
            for (int dc = 0; dc < 5; dc++)
                acc += gw.w[dr * 5 + dc] * gs[oy - 2 + dr][ox - 2 + dc];
        bs[r][c] = acc;
    }
    __syncthreads();

    for (int i = tid; i < 34 * 34; i += 256) {
        int r = i / 34, c = i - r * 34;
        int iy = by - 1 + r, ix = bx - 1 + c;
        float m = 0.f;
        if ((unsigned)iy < (unsigned)H && (unsigned)ix < (unsigned)W) {
            float a00 = bs[r][c],     a01 = bs[r][c + 1],     a02 = bs[r][c + 2];
            float a10 = bs[r + 1][c],                         a12 = bs[r + 1][c + 2];
            float a20 = bs[r + 2][c], a21 = bs[r + 2][c + 1], a22 = bs[r + 2][c + 2];
            float gxv = (a02 - a00) + 2.f * (a12 - a10) + (a22 - a20);
            float gyv = (a20 - a00) + 2.f * (a21 - a01) + (a22 - a02);
            m = sqrtf(gxv * gxv + gyv * gyv + 1e-6f);
        }
        ms[r][c] = m;
    }
    __syncthreads();

    const int tx = threadIdx.x;
    for (int k = 0; k < 4; k++) {
        int oy = threadIdx.y + 8 * k;
        int r = oy + 1, c = tx + 1;
        // recompute gx/gy with the identical expression -> bit-identical values
        float a00 = bs[r][c],     a01 = bs[r][c + 1],     a02 = bs[r][c + 2];
        float a10 = bs[r + 1][c],                         a12 = bs[r + 1][c + 2];
        float a20 = bs[r + 2][c], a21 = bs[r + 2][c + 1], a22 = bs[r + 2][c + 2];
        float gxv = (a02 - a00) + 2.f * (a12 - a10) + (a22 - a20);
        float gyv = (a20 - a00) + 2.f * (a21 - a01) + (a22 - a02);
        float deg = atan2f(gyv, gxv) * 57.29577951308232f;
        int kk = (int)rintf(deg / 45.0f);                    // half-even like jnp.round
        int pos = kk & 7, neg = (kk + 4) & 7;
        float mc = ms[r][c];
        float csp = mc - ms[r + c_dr[pos]][c + c_dc[pos]];
        float csn = mc - ms[r + c_dr[neg]][c + c_dc[neg]];
        float mo = (fminf(csp, csn) > 0.0f) ? mc : 0.0f;
        outMag[b * NPIX + (by + oy) * W + bx + tx] = mo;

        bool strong = mo > 0.2f;
        bool weak   = (mo > 0.1f) && !strong;
        unsigned sbits = __ballot_sync(0xffffffffu, strong);
        unsigned wbits = __ballot_sync(0xffffffffu, weak);
        if (tx == 0) {
            int wrow = ((b << 10) + by + oy) * WPR + blockIdx.x;
            g_sb[wrow] = sbits;
            g_wb[wrow] = wbits;
        }
    }
}

__global__ void k_reset() {
    if (threadIdx.x == 0) { g_bar = 0; g_epoch = 0; g_flag[0] = 0; g_flag[1] = 0; }
}

// -------- hysteresis: 128 regions of 128x256 bits, smem-resident flood fill --
// 128 blocks x 256 threads <= 148 SMs -> co-resident, sw epoch barrier legal.
__global__ void __launch_bounds__(256, 1) k_hyst(float* __restrict__ edges) {
    __shared__ unsigned Ssm[130][11];   // strong bits, halo 1 row/word each side
    __shared__ unsigned Wsm[128][9];    // weak bits, interior only
    __shared__ int s_chg, s_any;
    __shared__ unsigned s_f;
    const int tid = threadIdx.x;
    const int lane = tid & 31, wid = tid >> 5;
    const unsigned F = 0xffffffffu;

    // region decomposition: 4 batches x 8 row-regions x 4 word-regions = 128
    const int blk = blockIdx.x;
    const int b = blk >> 5, rr = (blk >> 2) & 7, wr = blk & 3;
    const int y0 = rr * 128, wx0 = wr * 8;
    const int gbase = ((b << 10) + y0) * WPR + wx0;

    const int band = wid >> 1, grp = wid & 1;     // 4 bands x 2 word-groups
    const int rbase = 1 + band * 32;

    unsigned pass = 0;
    for (;;) {
        // ---- load region into smem ----
        if (tid == 0) s_any = 0;
        for (int i = tid; i < 128 * 8; i += 256) {
            int r = i >> 3, w = i & 7;
            Ssm[1 + r][1 + w] = __ldcg(&g_sb[gbase + r * WPR + w]);
            Wsm[r][w]         = __ldcg(&g_wb[gbase + r * WPR + w]);
        }
        if (tid < 20) {                         // top/bottom halo rows (10 words)
            int top = tid < 10;
            int w = tid % 10;
            int gy = y0 + (top ? -1 : 128);
            int gw = wx0 - 1 + w;
            unsigned v = 0;
            if ((unsigned)gy < 1024u && (unsigned)gw < 32u)
                v = __ldcg(&g_sb[((b << 10) + gy) * WPR + gw]);
            Ssm[top ? 0 : 129][w] = v;
        }
        {                                       // left/right halo columns
            int r = tid & 127, side = tid >> 7;
            int gw = side ? wx0 + 8 : wx0 - 1;
            unsigned v = 0;
            if ((unsigned)gw < 32u)
                v = __ldcg(&g_sb[((b << 10) + y0 + r) * WPR + gw]);
            Ssm[1 + r][side ? 9 : 0] = v;
        }
        __syncthreads();

        // ---- in-block flood to convergence ----
        for (;;) {
            if (tid == 0) s_chg = 0;
            __syncthreads();
            bool ch = false;
            #pragma unroll
            for (int wc = 0; wc < 4; wc++) {
                int col = 1 + grp * 4 + wc;
                unsigned S  = Ssm[rbase + lane][col];
                unsigned Cw = Wsm[band * 32 + lane][grp * 4 + wc];
                unsigned Lw = Ssm[rbase + lane][col - 1];
                unsigned Rw = Ssm[rbase + lane][col + 1];
                unsigned myLR = ((Lw >> 31) & 1u) | ((Rw & 1u) << 31);
                unsigned upLR = __shfl_up_sync(F, myLR, 1);
                unsigned dnLR = __shfl_down_sync(F, myLR, 1);
                unsigned Us = 0, Ds = 0;
                if (lane == 0) {
                    Us = Ssm[rbase - 1][col];
                    unsigned ULs = Ssm[rbase - 1][col - 1];
                    unsigned URs = Ssm[rbase - 1][col + 1];
                    upLR = ((ULs >> 31) & 1u) | ((URs & 1u) << 31);
                }
                if (lane == 31) {
                    Ds = Ssm[rbase + 32][col];
                    unsigned DLs = Ssm[rbase + 32][col - 1];
                    unsigned DRs = Ssm[rbase + 32][col + 1];
                    dnLR = ((DLs >> 31) & 1u) | ((DRs & 1u) << 31);
                }
                unsigned Hfix = myLR | upLR | dnLR;
                if (lane == 0)  Hfix |= Us | (Us << 1) | (Us >> 1);
                if (lane == 31) Hfix |= Ds | (Ds << 1) | (Ds >> 1);

                unsigned S0 = S;
                for (;;) {
                    unsigned up = __shfl_up_sync(F, S, 1);   if (lane == 0)  up = 0;
                    unsigned dn = __shfl_down_sync(F, S, 1); if (lane == 31) dn = 0;
                    unsigned a = up | dn;
                    unsigned dil = a | (a << 1) | (a >> 1) | (S << 1) | (S >> 1) | Hfix;
                    unsigned nS = S | (Cw & dil);
                    if (!__any_sync(F, nS != S)) break;
                    S = nS;
                }
                if (S != S0) { Ssm[rbase + lane][col] = S; ch = true; }
            }
            if (__any_sync(F, ch) && lane == 0) { s_chg = 1; s_any = 1; }
            __syncthreads();
            if (!s_chg) break;
        }

        // ---- writeback (only if region changed) ----
        if (s_any) {
            for (int i = tid; i < 128 * 8; i += 256) {
                int r = i >> 3, w = i & 7;
                __stcg(&g_sb[gbase + r * WPR + w], Ssm[1 + r][1 + w]);
            }
            __threadfence();
        }
        __syncthreads();

        // ---- epoch barrier + global convergence flag ----
        if (tid == 0) {
            if (s_any) atomicOr(&g_flag[pass & 1], 1u);
            unsigned a = atomicAdd(&g_bar, 1u);
            unsigned target = pass + 1;
            if (a == gridDim.x - 1) {
                g_bar = 0;
                g_flag[(pass + 1) & 1] = 0;     // clean flag for next pass
                __threadfence();
                atomicAdd(&g_epoch, 1u);
            } else {
                while (*(volatile unsigned*)&g_epoch < target) __nanosleep(64);
            }
            s_f = *(volatile unsigned*)&g_flag[pass & 1];
        }
        __syncthreads();
        unsigned f = s_f;
        pass++;
        if (!f) break;
        __syncthreads();
    }

    // ---- expand final strong bits to float edges (coalesced) ----
    const int gwarp = blockIdx.x * 8 + wid;     // 0..1023
    for (int wi = gwarp; wi < NWORDS; wi += 1024) {
        unsigned bits = __ldcg(&g_sb[wi]);
        edges[(size_t)wi * 32 + lane] = ((bits >> lane) & 1u) ? 1.0f : 0.0f;
    }
}

// ---------------------------------------------------------------------------
extern "C" void kernel_launch(void* const* d_in, const int* in_sizes, int n_in,
                              void* d_out, int out_size) {
    const float* x = (const float*)d_in[0];
    float* out = (float*)d_out;

    // Gaussian weights (identical construction to the validated kernel)
    GaussW gw;
    float g1[5];
    for (int i = 0; i < 5; i++) {
        double d = (double)i - 2.0;
        g1[i] = (float)exp(-d * d / 2.0);
    }
    float s = 0.f;
    for (int i = 0; i < 5; i++) s += g1[i];
    for (int i = 0; i < 5; i++) g1[i] = g1[i] / s;
    for (int i = 0; i < 5; i++)
        for (int j = 0; j < 5; j++)
            gw.w[i * 5 + j] = g1[i] * g1[j];

    dim3 blk(32, 8), grd(32, 32, NB);
    k_front<<<grd, blk>>>(x, gw, out);      // magnitude -> out[0 .. TOT)
    k_reset<<<1, 32>>>();
    k_hyst<<<128, 256>>>(out + TOT);        // edges -> out[TOT .. 2*TOT)
    (void)in_sizes; (void)n_in; (void)out_size;
}